// round 10
// baseline (speedup 1.0000x reference)
#include <cuda_runtime.h>
#include <cstdint>

// Problem constants
#define BB 4
#define SS 8192
#define DD 64
#define NH 8
#define NB 128   // n_buckets

#define OUT_ELEMS  (BB * SS * DD)   // 2,097,152
#define BKT_ELEMS  (BB * NH * SS)   // 262,144

#define TPB     256   // tokens per block
#define THREADS 256
#define NBLK    ((BB * SS) / TPB)   // 128 blocks
#define QS      260   // qT row stride in floats (260*4 % 16 == 0 -> u64x2 loads ok)

#define SMEM_QT_FLOATS (64 * QS)          // 16640 floats = 66,560 B
#define SMEM_RS2_U64   (64 * 64)          // 4096 u64    = 32,768 B
#define SMEM_BYTES (SMEM_QT_FLOATS * 4 + SMEM_RS2_U64 * 8)   // 99,328 B

typedef unsigned long long ull;

__device__ __forceinline__ ull pack2(float x) {
    ull r;
    asm("mov.b64 %0, {%1, %1};" : "=l"(r) : "f"(x));
    return r;
}
__device__ __forceinline__ void fma2(ull& a, ull x, ull y) {
    // packed fp32x2 FMA (Blackwell): 2 FMAs per lane per instruction
    asm("fma.rn.f32x2 %0, %1, %2, %0;" : "+l"(a) : "l"(x), "l"(y));
}
__device__ __forceinline__ float lo32(ull a) {
    return __uint_as_float((unsigned)(a & 0xffffffffull));
}
__device__ __forceinline__ float hi32(ull a) {
    return __uint_as_float((unsigned)(a >> 32));
}

// ---------------------------------------------------------------------------
// Fused kernel:
//   (a) out[0:OUT] = v   (the masked LSH attention collapses to an exact copy)
//   (b) out_b[b, h*S + t] = argmax_i concat(r, -r) + h*NB,
//       r[i] = sum_d qk[b,t,d] * rot[d, h, i]
//
// 128 CTAs x 256 threads (1 CTA/SM, 8 warps). Thread tile: 8 tokens x 8 i.
// FFMA2 accumulators pair adjacent tokens (natural u64 pairs in transposed
// qT); rot is staged PRE-DUPLICATED as (r,r) u64 pairs in smem so the hot
// loop has zero MOVs. Loads for d+1 are software-pipelined into a register
// double buffer so LDS latency hides under the 32 FFMA2 of iteration d.
// ---------------------------------------------------------------------------
__global__ void __launch_bounds__(THREADS, 1)
lsh_fused_kernel(const float* __restrict__ qk,
                 const float* __restrict__ rot,
                 const float* __restrict__ v,
                 float* __restrict__ out,
                 float* __restrict__ out_b,
                 int do_copy, int do_bkt) {
    extern __shared__ float sm[];
    float* qT = sm;                                    // [d][t_local], stride QS
    ull*   rs2 = (ull*)(sm + SMEM_QT_FLOATS);          // [d][i] duplicated pairs

    const int tid   = threadIdx.x;
    const int g0    = blockIdx.x * TPB;
    const int b     = g0 >> 13;            // g0 / SS
    const int tbase = g0 & (SS - 1);

    // (a) copy this block's v slice (hides under compute)
    if (do_copy) {
        const float4* vs = (const float4*)v + (size_t)g0 * (DD / 4);
        float4*       os = (float4*)out    + (size_t)g0 * (DD / 4);
        #pragma unroll 4
        for (int e = tid; e < TPB * DD / 4; e += THREADS) os[e] = vs[e];
    }
    if (!do_bkt) return;

    // stage q transposed (coalesced global reads)
    for (int e = tid; e < TPB * 64; e += THREADS) {
        int tl = e >> 6, d = e & 63;
        qT[d * QS + tl] = qk[(size_t)(g0 + tl) * DD + d];
    }

    const int part = tid & 7;    // i in [part*8, part*8+8)
    const int tg   = tid >> 3;   // tokens tg*8 .. tg*8+7
    const float* qp = qT + tg * 8;
    const ull*   rp = rs2 + part * 8;
    const int i0 = part * 8;

    for (int h = 0; h < NH; ++h) {
        __syncthreads();   // also covers qT readiness on h==0
        // stage rot[:, h, :] duplicated -> rs2 (coalesced gmem; 8B smem stores)
        for (int e = tid; e < 64 * 64; e += THREADS) {
            int d = e >> 6, i = e & 63;
            rs2[e] = pack2(rot[d * (NH * 64) + h * 64 + i]);
        }
        __syncthreads();

        ull acc[4][8];   // [token-pair][i]; 0ull == (0.f, 0.f)
        #pragma unroll
        for (int p = 0; p < 4; ++p)
            #pragma unroll
            for (int k = 0; k < 8; ++k) acc[p][k] = 0ull;

        // software-pipelined over d: double-buffered operand registers
        ulonglong2 qA[2], qB[2], r0[2], r1[2], r2[2], r3[2];
        qA[0] = *(const ulonglong2*)(qp);
        qB[0] = *(const ulonglong2*)(qp + 4);
        r0[0] = *(const ulonglong2*)(rp);
        r1[0] = *(const ulonglong2*)(rp + 2);
        r2[0] = *(const ulonglong2*)(rp + 4);
        r3[0] = *(const ulonglong2*)(rp + 6);

        #pragma unroll 8
        for (int d = 0; d < 64; ++d) {
            const int cur = d & 1, nxt = cur ^ 1;
            if (d < 63) {
                const float* qn = qp + (d + 1) * QS;
                const ull*   rn = rp + (d + 1) * 64;
                qA[nxt] = *(const ulonglong2*)(qn);
                qB[nxt] = *(const ulonglong2*)(qn + 4);
                r0[nxt] = *(const ulonglong2*)(rn);
                r1[nxt] = *(const ulonglong2*)(rn + 2);
                r2[nxt] = *(const ulonglong2*)(rn + 4);
                r3[nxt] = *(const ulonglong2*)(rn + 6);
            }
            ull qq[4] = {qA[cur].x, qA[cur].y, qB[cur].x, qB[cur].y};
            ull rr[8] = {r0[cur].x, r0[cur].y, r1[cur].x, r1[cur].y,
                         r2[cur].x, r2[cur].y, r3[cur].x, r3[cur].y};
            #pragma unroll
            for (int p = 0; p < 4; ++p)
                #pragma unroll
                for (int k = 0; k < 8; ++k)
                    fma2(acc[p][k], qq[p], rr[k]);
        }

        // per-token argmax over [r, -r]; strict '>' = first-occurrence ties
        #pragma unroll
        for (int p = 0; p < 4; ++p) {
            #pragma unroll
            for (int half = 0; half < 2; ++half) {
                float vv[8];
                #pragma unroll
                for (int k = 0; k < 8; ++k)
                    vv[k] = half ? hi32(acc[p][k]) : lo32(acc[p][k]);

                float bv = vv[0]; int bi = i0;
                #pragma unroll
                for (int k = 1; k < 8; ++k)
                    if (vv[k] > bv) { bv = vv[k]; bi = i0 + k; }
                #pragma unroll
                for (int k = 0; k < 8; ++k) {
                    float nv = -vv[k];
                    if (nv > bv) { bv = nv; bi = 64 + i0 + k; }
                }
                // reduce across 8 parts (consecutive lanes)
                #pragma unroll
                for (int off = 4; off >= 1; off >>= 1) {
                    float ov = __shfl_down_sync(0xFFFFFFFFu, bv, off);
                    int   oi = __shfl_down_sync(0xFFFFFFFFu, bi, off);
                    if (ov > bv || (ov == bv && oi < bi)) { bv = ov; bi = oi; }
                }
                if (part == 0) {
                    int t = tbase + tg * 8 + p * 2 + half;
                    out_b[(size_t)b * (NH * SS) + (size_t)h * SS + t] =
                        (float)(bi + h * NB);
                }
            }
        }
    }
}

extern "C" void kernel_launch(void* const* d_in, const int* in_sizes, int n_in,
                              void* d_out, int out_size) {
    const float* qk  = (const float*)d_in[0];
    const float* v   = (const float*)d_in[1];
    const float* rot = (const float*)d_in[2];
    float* out = (float*)d_out;

    cudaFuncSetAttribute(lsh_fused_kernel,
                         cudaFuncAttributeMaxDynamicSharedMemorySize,
                         SMEM_BYTES);

    int do_copy = (out_size >= OUT_ELEMS) ? 1 : 0;
    int do_bkt  = (out_size == OUT_ELEMS + BKT_ELEMS || out_size == BKT_ELEMS) ? 1 : 0;
    float* out_b = (out_size == BKT_ELEMS) ? out : out + OUT_ELEMS;

    lsh_fused_kernel<<<NBLK, THREADS, SMEM_BYTES>>>(
        qk, rot, v, out, out_b, do_copy, do_bkt);
}

// round 12
// speedup vs baseline: 1.0082x; 1.0082x over previous
#include <cuda_runtime.h>
#include <cstdint>

// Problem constants
#define BB 4
#define SS 8192
#define DD 64
#define NH 8
#define NB 128   // n_buckets

#define OUT_ELEMS  (BB * SS * DD)   // 2,097,152
#define BKT_ELEMS  (BB * NH * SS)   // 262,144

#define TPB     256   // tokens per block
#define THREADS 256
#define NBLK    ((BB * SS) / TPB)   // 128 blocks
#define QS      260   // qT row stride in floats (260*4 % 16 == 0 -> 16B loads ok)

#define SMEM_QT_FLOATS (64 * QS)          // 16640 floats = 66,560 B
#define SMEM_RS2_U64   (64 * 64)          // 4096 u64    = 32,768 B
#define SMEM_BYTES (SMEM_QT_FLOATS * 4 + SMEM_RS2_U64 * 8)   // 99,328 B

typedef unsigned long long ull;

__device__ __forceinline__ ull pack2(float x) {
    ull r;
    asm("mov.b64 %0, {%1, %1};" : "=l"(r) : "f"(x));
    return r;
}
__device__ __forceinline__ void fma2(ull& a, ull x, ull y) {
    // packed fp32x2 FMA (Blackwell): 2 FMAs per lane per instruction
    asm("fma.rn.f32x2 %0, %1, %2, %0;" : "+l"(a) : "l"(x), "l"(y));
}
__device__ __forceinline__ float lo32(ull a) {
    return __uint_as_float((unsigned)(a & 0xffffffffull));
}
__device__ __forceinline__ float hi32(ull a) {
    return __uint_as_float((unsigned)(a >> 32));
}

// ---------------------------------------------------------------------------
// Fused kernel:
//   (a) out[0:OUT] = v   (the masked LSH attention collapses to an exact copy)
//   (b) out_b[b, h*S + t] = argmax_i concat(r, -r) + h*NB,
//       r[i] = sum_d qk[b,t,d] * rot[d, h, i]
//
// 128 CTAs x 256 threads (1 CTA/SM, 8 warps). Thread tile: 8 tokens x 8 i.
// FFMA2 accumulators pair adjacent tokens (natural u64 pairs in transposed
// qT). rot is staged PRE-DUPLICATED as (r,r) u64 pairs in smem so the hot
// loop has zero MOVs: 6 LDS.128 + 32 FFMA2 per thread-d. No manual
// pipelining (R9/R10 showed any extra register state causes spills);
// ptxas schedules the unroll-4 body itself.
// ---------------------------------------------------------------------------
__global__ void __launch_bounds__(THREADS, 1)
lsh_fused_kernel(const float* __restrict__ qk,
                 const float* __restrict__ rot,
                 const float* __restrict__ v,
                 float* __restrict__ out,
                 float* __restrict__ out_b,
                 int do_copy, int do_bkt) {
    extern __shared__ float sm[];
    float* qT  = sm;                              // [d][t_local], stride QS
    ull*   rs2 = (ull*)(sm + SMEM_QT_FLOATS);     // [d][i] duplicated (r,r)

    const int tid   = threadIdx.x;
    const int g0    = blockIdx.x * TPB;
    const int b     = g0 >> 13;            // g0 / SS
    const int tbase = g0 & (SS - 1);

    // (a) copy this block's v slice (hides under compute)
    if (do_copy) {
        const float4* vs = (const float4*)v + (size_t)g0 * (DD / 4);
        float4*       os = (float4*)out    + (size_t)g0 * (DD / 4);
        #pragma unroll 4
        for (int e = tid; e < TPB * DD / 4; e += THREADS) os[e] = vs[e];
    }
    if (!do_bkt) return;

    // stage q transposed (coalesced global reads)
    for (int e = tid; e < TPB * 64; e += THREADS) {
        int tl = e >> 6, d = e & 63;
        qT[d * QS + tl] = qk[(size_t)(g0 + tl) * DD + d];
    }

    const int part = tid & 7;    // i in [part*8, part*8+8)
    const int tg   = tid >> 3;   // tokens tg*8 .. tg*8+7
    const float* qp = qT  + tg * 8;
    const ull*   rp = rs2 + part * 8;
    const int i0 = part * 8;

    for (int h = 0; h < NH; ++h) {
        __syncthreads();   // also covers qT readiness on h==0
        // stage rot[:, h, :] duplicated -> rs2 (coalesced gmem; 8B smem stores)
        for (int e = tid; e < 64 * 64; e += THREADS) {
            int d = e >> 6, i = e & 63;
            rs2[e] = pack2(rot[d * (NH * 64) + h * 64 + i]);
        }
        __syncthreads();

        ull acc[4][8];   // [token-pair][i]; 0ull == (0.f, 0.f)
        #pragma unroll
        for (int p = 0; p < 4; ++p)
            #pragma unroll
            for (int k = 0; k < 8; ++k) acc[p][k] = 0ull;

        #pragma unroll 4
        for (int d = 0; d < 64; ++d) {
            // q: 8 tokens = 4 natural u64 pairs (tokens contiguous in qT rows)
            ulonglong2 qA = *(const ulonglong2*)(qp + d * QS);
            ulonglong2 qB = *(const ulonglong2*)(qp + d * QS + 4);
            // r: 8 pre-duplicated pairs, 4 x LDS.128, zero MOVs
            ulonglong2 rA = *(const ulonglong2*)(rp + d * 64);
            ulonglong2 rB = *(const ulonglong2*)(rp + d * 64 + 2);
            ulonglong2 rC = *(const ulonglong2*)(rp + d * 64 + 4);
            ulonglong2 rD = *(const ulonglong2*)(rp + d * 64 + 6);
            ull qq[4] = {qA.x, qA.y, qB.x, qB.y};
            ull rr[8] = {rA.x, rA.y, rB.x, rB.y, rC.x, rC.y, rD.x, rD.y};
            #pragma unroll
            for (int p = 0; p < 4; ++p)
                #pragma unroll
                for (int k = 0; k < 8; ++k)
                    fma2(acc[p][k], qq[p], rr[k]);
        }

        // per-token argmax over [r, -r]; strict '>' = first-occurrence ties
        #pragma unroll
        for (int p = 0; p < 4; ++p) {
            #pragma unroll
            for (int half = 0; half < 2; ++half) {
                float vv[8];
                #pragma unroll
                for (int k = 0; k < 8; ++k)
                    vv[k] = half ? hi32(acc[p][k]) : lo32(acc[p][k]);

                float bv = vv[0]; int bi = i0;
                #pragma unroll
                for (int k = 1; k < 8; ++k)
                    if (vv[k] > bv) { bv = vv[k]; bi = i0 + k; }
                #pragma unroll
                for (int k = 0; k < 8; ++k) {
                    float nv = -vv[k];
                    if (nv > bv) { bv = nv; bi = 64 + i0 + k; }
                }
                // reduce across 8 parts (consecutive lanes)
                #pragma unroll
                for (int off = 4; off >= 1; off >>= 1) {
                    float ov = __shfl_down_sync(0xFFFFFFFFu, bv, off);
                    int   oi = __shfl_down_sync(0xFFFFFFFFu, bi, off);
                    if (ov > bv || (ov == bv && oi < bi)) { bv = ov; bi = oi; }
                }
                if (part == 0) {
                    int t = tbase + tg * 8 + p * 2 + half;
                    out_b[(size_t)b * (NH * SS) + (size_t)h * SS + t] =
                        (float)(bi + h * NB);
                }
            }
        }
    }
}

extern "C" void kernel_launch(void* const* d_in, const int* in_sizes, int n_in,
                              void* d_out, int out_size) {
    const float* qk  = (const float*)d_in[0];
    const float* v   = (const float*)d_in[1];
    const float* rot = (const float*)d_in[2];
    float* out = (float*)d_out;

    cudaFuncSetAttribute(lsh_fused_kernel,
                         cudaFuncAttributeMaxDynamicSharedMemorySize,
                         SMEM_BYTES);

    int do_copy = (out_size >= OUT_ELEMS) ? 1 : 0;
    int do_bkt  = (out_size == OUT_ELEMS + BKT_ELEMS || out_size == BKT_ELEMS) ? 1 : 0;
    float* out_b = (out_size == BKT_ELEMS) ? out : out + OUT_ELEMS;

    lsh_fused_kernel<<<NBLK, THREADS, SMEM_BYTES>>>(
        qk, rot, v, out, out_b, do_copy, do_bkt);
}

// round 13
// speedup vs baseline: 1.5783x; 1.5655x over previous
#include <cuda_runtime.h>
#include <cstdint>

// Problem constants
#define BB 4
#define SS 8192
#define DD 64
#define NH 8
#define NB 128   // n_buckets

#define OUT_ELEMS  (BB * SS * DD)   // 2,097,152
#define BKT_ELEMS  (BB * NH * SS)   // 262,144

#define TPB     128   // tokens per block
#define THREADS 256
#define NBLK    ((BB * SS) / TPB)   // 256 blocks (2 CTAs/SM over 148 SMs)
#define QS      132   // qT row stride in floats (132*4 = 528 B, 16B-multiple)

#define SMEM_QT_FLOATS (64 * QS)          // 8448 floats = 33,792 B
#define SMEM_RS2_U64   (64 * 64)          // 4096 u64   = 32,768 B
#define SMEM_BYTES (SMEM_QT_FLOATS * 4 + SMEM_RS2_U64 * 8)   // 66,560 B/CTA

typedef unsigned long long ull;

__device__ __forceinline__ ull pack2(float x) {
    ull r;
    asm("mov.b64 %0, {%1, %1};" : "=l"(r) : "f"(x));
    return r;
}
__device__ __forceinline__ void fma2(ull& a, ull x, ull y) {
    // packed fp32x2 FMA (Blackwell): 2 FMAs per lane per instruction
    asm("fma.rn.f32x2 %0, %1, %2, %0;" : "+l"(a) : "l"(x), "l"(y));
}
__device__ __forceinline__ float lo32(ull a) {
    return __uint_as_float((unsigned)(a & 0xffffffffull));
}
__device__ __forceinline__ float hi32(ull a) {
    return __uint_as_float((unsigned)(a >> 32));
}

// ---------------------------------------------------------------------------
// Fused kernel:
//   (a) out[0:OUT] = v   (the masked LSH attention collapses to an exact copy)
//   (b) out_b[b, h*S + t] = argmax_i concat(r, -r) + h*NB,
//       r[i] = sum_d qk[b,t,d] * rot[d, h, i]
//
// 256 CTAs x 256 threads, 2 CTAs/SM (launch_bounds(256,2), smem 66.5KB/CTA).
// Thread tile: 8 tokens x 4 i -> only 16 u64 accumulators (32 regs), leaving
// ample register headroom (R9/R10/R12 all spilled with the 8x8 tile's 64
// acc regs). part = tid&15 owns 4 i's; tg = tid>>4 owns 8 tokens.
// rot staged PRE-DUPLICATED as (r,r) u64 pairs -> hot loop is
// 4 x LDS.128 + 16 FFMA2 per thread-d, zero MOVs.
// ---------------------------------------------------------------------------
__global__ void __launch_bounds__(THREADS, 2)
lsh_fused_kernel(const float* __restrict__ qk,
                 const float* __restrict__ rot,
                 const float* __restrict__ v,
                 float* __restrict__ out,
                 float* __restrict__ out_b,
                 int do_copy, int do_bkt) {
    extern __shared__ float sm[];
    float* qT  = sm;                              // [d][t_local], stride QS
    ull*   rs2 = (ull*)(sm + SMEM_QT_FLOATS);     // [d][i] duplicated (r,r)

    const int tid   = threadIdx.x;
    const int g0    = blockIdx.x * TPB;
    const int b     = g0 >> 13;            // g0 / SS
    const int tbase = g0 & (SS - 1);

    // (a) copy this block's v slice (hides under compute)
    if (do_copy) {
        const float4* vs = (const float4*)v + (size_t)g0 * (DD / 4);
        float4*       os = (float4*)out    + (size_t)g0 * (DD / 4);
        #pragma unroll 4
        for (int e = tid; e < TPB * DD / 4; e += THREADS) os[e] = vs[e];
    }
    if (!do_bkt) return;

    // stage q transposed (coalesced global reads)
    for (int e = tid; e < TPB * 64; e += THREADS) {
        int tl = e >> 6, d = e & 63;
        qT[d * QS + tl] = qk[(size_t)(g0 + tl) * DD + d];
    }

    const int part = tid & 15;   // i in [part*4, part*4+4)
    const int tg   = tid >> 4;   // tokens tg*8 .. tg*8+7
    const float* qp = qT  + tg * 8;
    const ull*   rp = rs2 + part * 4;
    const int i0 = part * 4;

    for (int h = 0; h < NH; ++h) {
        __syncthreads();   // also covers qT readiness on h==0
        // stage rot[:, h, :] duplicated -> rs2 (coalesced gmem; 8B smem stores)
        for (int e = tid; e < 64 * 64; e += THREADS) {
            int d = e >> 6, i = e & 63;
            rs2[e] = pack2(rot[d * (NH * 64) + h * 64 + i]);
        }
        __syncthreads();

        ull acc[4][4];   // [token-pair][i]; 0ull == (0.f, 0.f)
        #pragma unroll
        for (int p = 0; p < 4; ++p)
            #pragma unroll
            for (int k = 0; k < 4; ++k) acc[p][k] = 0ull;

        #pragma unroll 4
        for (int d = 0; d < 64; ++d) {
            // q: 8 tokens = 4 natural u64 pairs (tokens contiguous in qT rows)
            ulonglong2 qA = *(const ulonglong2*)(qp + d * QS);
            ulonglong2 qB = *(const ulonglong2*)(qp + d * QS + 4);
            // r: 4 pre-duplicated pairs, 2 x LDS.128, zero MOVs
            ulonglong2 rA = *(const ulonglong2*)(rp + d * 64);
            ulonglong2 rB = *(const ulonglong2*)(rp + d * 64 + 2);
            ull qq[4] = {qA.x, qA.y, qB.x, qB.y};
            ull rr[4] = {rA.x, rA.y, rB.x, rB.y};
            #pragma unroll
            for (int p = 0; p < 4; ++p)
                #pragma unroll
                for (int k = 0; k < 4; ++k)
                    fma2(acc[p][k], qq[p], rr[k]);
        }

        // per-token argmax over [r, -r]; strict '>' = first-occurrence ties
        #pragma unroll
        for (int p = 0; p < 4; ++p) {
            #pragma unroll
            for (int half = 0; half < 2; ++half) {
                float vv[4];
                #pragma unroll
                for (int k = 0; k < 4; ++k)
                    vv[k] = half ? hi32(acc[p][k]) : lo32(acc[p][k]);

                float bv = vv[0]; int bi = i0;
                #pragma unroll
                for (int k = 1; k < 4; ++k)
                    if (vv[k] > bv) { bv = vv[k]; bi = i0 + k; }
                #pragma unroll
                for (int k = 0; k < 4; ++k) {
                    float nv = -vv[k];
                    if (nv > bv) { bv = nv; bi = 64 + i0 + k; }
                }
                // reduce across 16 parts (consecutive lanes); smaller global
                // index wins ties (first-occurrence semantics)
                #pragma unroll
                for (int off = 8; off >= 1; off >>= 1) {
                    float ov = __shfl_down_sync(0xFFFFFFFFu, bv, off);
                    int   oi = __shfl_down_sync(0xFFFFFFFFu, bi, off);
                    if (ov > bv || (ov == bv && oi < bi)) { bv = ov; bi = oi; }
                }
                if (part == 0) {
                    int t = tbase + tg * 8 + p * 2 + half;
                    out_b[(size_t)b * (NH * SS) + (size_t)h * SS + t] =
                        (float)(bi + h * NB);
                }
            }
        }
    }
}

extern "C" void kernel_launch(void* const* d_in, const int* in_sizes, int n_in,
                              void* d_out, int out_size) {
    const float* qk  = (const float*)d_in[0];
    const float* v   = (const float*)d_in[1];
    const float* rot = (const float*)d_in[2];
    float* out = (float*)d_out;

    cudaFuncSetAttribute(lsh_fused_kernel,
                         cudaFuncAttributeMaxDynamicSharedMemorySize,
                         SMEM_BYTES);

    int do_copy = (out_size >= OUT_ELEMS) ? 1 : 0;
    int do_bkt  = (out_size == OUT_ELEMS + BKT_ELEMS || out_size == BKT_ELEMS) ? 1 : 0;
    float* out_b = (out_size == BKT_ELEMS) ? out : out + OUT_ELEMS;

    lsh_fused_kernel<<<NBLK, THREADS, SMEM_BYTES>>>(
        qk, rot, v, out, out_b, do_copy, do_bkt);
}

// round 16
// speedup vs baseline: 1.6044x; 1.0165x over previous
#include <cuda_runtime.h>
#include <cstdint>

// Problem constants
#define BB 4
#define SS 8192
#define DD 64
#define NH 8
#define NB 128   // n_buckets

#define OUT_ELEMS  (BB * SS * DD)   // 2,097,152
#define BKT_ELEMS  (BB * NH * SS)   // 262,144

#define TPB     128   // tokens per block
#define THREADS 256
#define NBLK    ((BB * SS) / TPB)   // 256 blocks (2 CTAs/SM over 148 SMs)
#define QS      132   // qT row stride in floats (132*4 = 528 B, 16B-multiple)

#define SMEM_QT_FLOATS (64 * QS)          // 8448 floats = 33,792 B
#define SMEM_RS2_U64   (64 * 64)          // 4096 u64   = 32,768 B
#define SMEM_BYTES (SMEM_QT_FLOATS * 4 + SMEM_RS2_U64 * 8)   // 66,560 B/CTA

typedef unsigned long long ull;

__device__ __forceinline__ ull pack2(float x) {
    ull r;
    asm("mov.b64 %0, {%1, %1};" : "=l"(r) : "f"(x));
    return r;
}
__device__ __forceinline__ void fma2(ull& a, ull x, ull y) {
    // packed fp32x2 FMA (Blackwell): 2 FMAs per lane per instruction
    asm("fma.rn.f32x2 %0, %1, %2, %0;" : "+l"(a) : "l"(x), "l"(y));
}
__device__ __forceinline__ float lo32(ull a) {
    return __uint_as_float((unsigned)(a & 0xffffffffull));
}
__device__ __forceinline__ float hi32(ull a) {
    return __uint_as_float((unsigned)(a >> 32));
}

// ---------------------------------------------------------------------------
// Fused kernel:
//   (a) out[0:OUT] = v   (the masked LSH attention collapses to an exact copy)
//   (b) out_b[b, h*S + t] = argmax_i concat(r, -r) + h*NB,
//       r[i] = sum_d qk[b,t,d] * rot[d, h, i]
//
// 256 CTAs x 256 threads, 2 CTAs/SM (launch_bounds(256,2), smem 66.5KB/CTA).
// Thread tile: 8 tokens x 4 i -> only 16 u64 accumulators (32 regs), leaving
// ample register headroom (R9/R10/R12 all spilled with the 8x8 tile's 64
// acc regs). part = tid&15 owns 4 i's; tg = tid>>4 owns 8 tokens.
// rot staged PRE-DUPLICATED as (r,r) u64 pairs -> hot loop is
// 4 x LDS.128 + 16 FFMA2 per thread-d, zero MOVs.
// ---------------------------------------------------------------------------
__global__ void __launch_bounds__(THREADS, 2)
lsh_fused_kernel(const float* __restrict__ qk,
                 const float* __restrict__ rot,
                 const float* __restrict__ v,
                 float* __restrict__ out,
                 float* __restrict__ out_b,
                 int do_copy, int do_bkt) {
    extern __shared__ float sm[];
    float* qT  = sm;                              // [d][t_local], stride QS
    ull*   rs2 = (ull*)(sm + SMEM_QT_FLOATS);     // [d][i] duplicated (r,r)

    const int tid   = threadIdx.x;
    const int g0    = blockIdx.x * TPB;
    const int b     = g0 >> 13;            // g0 / SS
    const int tbase = g0 & (SS - 1);

    // (a) copy this block's v slice (hides under compute)
    if (do_copy) {
        const float4* vs = (const float4*)v + (size_t)g0 * (DD / 4);
        float4*       os = (float4*)out    + (size_t)g0 * (DD / 4);
        #pragma unroll 4
        for (int e = tid; e < TPB * DD / 4; e += THREADS) os[e] = vs[e];
    }
    if (!do_bkt) return;

    // stage q transposed (coalesced global reads)
    for (int e = tid; e < TPB * 64; e += THREADS) {
        int tl = e >> 6, d = e & 63;
        qT[d * QS + tl] = qk[(size_t)(g0 + tl) * DD + d];
    }

    const int part = tid & 15;   // i in [part*4, part*4+4)
    const int tg   = tid >> 4;   // tokens tg*8 .. tg*8+7
    const float* qp = qT  + tg * 8;
    const ull*   rp = rs2 + part * 4;
    const int i0 = part * 4;

    for (int h = 0; h < NH; ++h) {
        __syncthreads();   // also covers qT readiness on h==0
        // stage rot[:, h, :] duplicated -> rs2 (coalesced gmem; 8B smem stores)
        for (int e = tid; e < 64 * 64; e += THREADS) {
            int d = e >> 6, i = e & 63;
            rs2[e] = pack2(rot[d * (NH * 64) + h * 64 + i]);
        }
        __syncthreads();

        ull acc[4][4];   // [token-pair][i]; 0ull == (0.f, 0.f)
        #pragma unroll
        for (int p = 0; p < 4; ++p)
            #pragma unroll
            for (int k = 0; k < 4; ++k) acc[p][k] = 0ull;

        #pragma unroll 4
        for (int d = 0; d < 64; ++d) {
            // q: 8 tokens = 4 natural u64 pairs (tokens contiguous in qT rows)
            ulonglong2 qA = *(const ulonglong2*)(qp + d * QS);
            ulonglong2 qB = *(const ulonglong2*)(qp + d * QS + 4);
            // r: 4 pre-duplicated pairs, 2 x LDS.128, zero MOVs
            ulonglong2 rA = *(const ulonglong2*)(rp + d * 64);
            ulonglong2 rB = *(const ulonglong2*)(rp + d * 64 + 2);
            ull qq[4] = {qA.x, qA.y, qB.x, qB.y};
            ull rr[4] = {rA.x, rA.y, rB.x, rB.y};
            #pragma unroll
            for (int p = 0; p < 4; ++p)
                #pragma unroll
                for (int k = 0; k < 4; ++k)
                    fma2(acc[p][k], qq[p], rr[k]);
        }

        // per-token argmax over [r, -r]; strict '>' = first-occurrence ties
        #pragma unroll
        for (int p = 0; p < 4; ++p) {
            #pragma unroll
            for (int half = 0; half < 2; ++half) {
                float vv[4];
                #pragma unroll
                for (int k = 0; k < 4; ++k)
                    vv[k] = half ? hi32(acc[p][k]) : lo32(acc[p][k]);

                float bv = vv[0]; int bi = i0;
                #pragma unroll
                for (int k = 1; k < 4; ++k)
                    if (vv[k] > bv) { bv = vv[k]; bi = i0 + k; }
                #pragma unroll
                for (int k = 0; k < 4; ++k) {
                    float nv = -vv[k];
                    if (nv > bv) { bv = nv; bi = 64 + i0 + k; }
                }
                // reduce across 16 parts (consecutive lanes); smaller global
                // index wins ties (first-occurrence semantics)
                #pragma unroll
                for (int off = 8; off >= 1; off >>= 1) {
                    float ov = __shfl_down_sync(0xFFFFFFFFu, bv, off);
                    int   oi = __shfl_down_sync(0xFFFFFFFFu, bi, off);
                    if (ov > bv || (ov == bv && oi < bi)) { bv = ov; bi = oi; }
                }
                if (part == 0) {
                    int t = tbase + tg * 8 + p * 2 + half;
                    out_b[(size_t)b * (NH * SS) + (size_t)h * SS + t] =
                        (float)(bi + h * NB);
                }
            }
        }
    }
}

extern "C" void kernel_launch(void* const* d_in, const int* in_sizes, int n_in,
                              void* d_out, int out_size) {
    const float* qk  = (const float*)d_in[0];
    const float* v   = (const float*)d_in[1];
    const float* rot = (const float*)d_in[2];
    float* out = (float*)d_out;

    cudaFuncSetAttribute(lsh_fused_kernel,
                         cudaFuncAttributeMaxDynamicSharedMemorySize,
                         SMEM_BYTES);

    int do_copy = (out_size >= OUT_ELEMS) ? 1 : 0;
    int do_bkt  = (out_size == OUT_ELEMS + BKT_ELEMS || out_size == BKT_ELEMS) ? 1 : 0;
    float* out_b = (out_size == BKT_ELEMS) ? out : out + OUT_ELEMS;

    lsh_fused_kernel<<<NBLK, THREADS, SMEM_BYTES>>>(
        qk, rot, v, out, out_b, do_copy, do_bkt);
}